// round 3
// baseline (speedup 1.0000x reference)
#include <cuda_runtime.h>
#include <math.h>

#define BB 64
#define CC 1024
#define QQ 256
#define DD 128
#define OUTD (4*DD)
#define NEGV (-1e30f)
#define NCHUNK 8

// ---- scratch (device globals: allocation-free) ----
__device__ float g_S[(size_t)BB*CC*QQ];      // raw S, 64 MB
__device__ float g_s0[BB*CC];
__device__ float g_s1[BB*QQ];
__device__ float g_pm[BB*NCHUNK*QQ];
__device__ float g_ps[BB*NCHUNK*QQ];
__device__ float g_colM[BB*QQ];
__device__ float g_colZ[BB*QQ];
__device__ float g_rowM[BB*CC];
__device__ float g_rowZ[BB*CC];
__device__ float g_A[(size_t)BB*QQ*DD];      // S_T @ x_cont, 8 MB

// ---------------------------------------------------------------------------
// projections: s0 = x_cont @ W0, s1 = x_ques @ W1  (one warp per row)
// ---------------------------------------------------------------------------
__device__ __forceinline__ float row_dot(const float* __restrict__ xr,
                                         const float* __restrict__ W, int lane)
{
    float s = 0.f;
#pragma unroll
    for (int d = 0; d < DD; d += 32) s += xr[d + lane] * W[d + lane];
#pragma unroll
    for (int o = 16; o > 0; o >>= 1) s += __shfl_xor_sync(0xffffffffu, s, o);
    return s;
}

__global__ void k_s0(const float* __restrict__ x, const float* __restrict__ W)
{
    int warp = (blockIdx.x * blockDim.x + threadIdx.x) >> 5;
    int lane = threadIdx.x & 31;
    if (warp >= BB*CC) return;
    float s = row_dot(x + (size_t)warp * DD, W, lane);
    if (lane == 0) g_s0[warp] = s;
}

__global__ void k_s1(const float* __restrict__ x, const float* __restrict__ W)
{
    int warp = (blockIdx.x * blockDim.x + threadIdx.x) >> 5;
    int lane = threadIdx.x & 31;
    if (warp >= BB*QQ) return;
    float s = row_dot(x + (size_t)warp * DD, W, lane);
    if (lane == 0) g_s1[warp] = s;
}

// ---------------------------------------------------------------------------
// K1: S[b,c,q] = sum_d (xc[b,c,d]*W2[d]) * xq[b,q,d] + s0 + s1 + bias
// 64x64 tile, K=128, 16x16 threads, 4x4 microtile
// ---------------------------------------------------------------------------
__global__ __launch_bounds__(256) void k1_S(const float* __restrict__ xc,
                                            const float* __restrict__ xq,
                                            const float* __restrict__ W2,
                                            const float* __restrict__ bias)
{
    __shared__ float As[64][17];
    __shared__ float Bs[64][17];
    __shared__ float W2s[DD];
    int b  = blockIdx.z;
    int c0 = blockIdx.y * 64;
    int q0 = blockIdx.x * 64;
    int tx = threadIdx.x, ty = threadIdx.y;
    int tid = ty * 16 + tx;
    if (tid < DD) W2s[tid] = W2[tid];

    const float* xcb = xc + ((size_t)(b*CC + c0))*DD;
    const float* xqb = xq + ((size_t)(b*QQ + q0))*DD;
    int lrow = tid >> 2;
    int lk   = (tid & 3) * 4;
    float acc[4][4] = {};
    __syncthreads();

    for (int k0 = 0; k0 < DD; k0 += 16) {
        float4 a4 = *(const float4*)(xcb + (size_t)lrow*DD + k0 + lk);
        float4 b4 = *(const float4*)(xqb + (size_t)lrow*DD + k0 + lk);
        As[lrow][lk+0] = a4.x * W2s[k0+lk+0];
        As[lrow][lk+1] = a4.y * W2s[k0+lk+1];
        As[lrow][lk+2] = a4.z * W2s[k0+lk+2];
        As[lrow][lk+3] = a4.w * W2s[k0+lk+3];
        Bs[lrow][lk+0] = b4.x;
        Bs[lrow][lk+1] = b4.y;
        Bs[lrow][lk+2] = b4.z;
        Bs[lrow][lk+3] = b4.w;
        __syncthreads();
#pragma unroll
        for (int k = 0; k < 16; k++) {
            float a[4], bq[4];
#pragma unroll
            for (int i = 0; i < 4; i++) a[i]  = As[ty*4+i][k];
#pragma unroll
            for (int j = 0; j < 4; j++) bq[j] = Bs[tx*4+j][k];
#pragma unroll
            for (int i = 0; i < 4; i++)
#pragma unroll
                for (int j = 0; j < 4; j++) acc[i][j] += a[i]*bq[j];
        }
        __syncthreads();
    }

    float bi = bias[0];
    int q = q0 + tx*4;
#pragma unroll
    for (int i = 0; i < 4; i++) {
        int c = c0 + ty*4 + i;
        float s0v = g_s0[b*CC + c] + bi;
        float4 o;
        o.x = acc[i][0] + s0v + g_s1[b*QQ + q+0];
        o.y = acc[i][1] + s0v + g_s1[b*QQ + q+1];
        o.z = acc[i][2] + s0v + g_s1[b*QQ + q+2];
        o.w = acc[i][3] + s0v + g_s1[b*QQ + q+3];
        *(float4*)&g_S[((size_t)(b*CC + c))*QQ + q] = o;
    }
}

// ---------------------------------------------------------------------------
// K2a: per-(b,q) online max/sumexp over c (partial per 128-c chunk)
// ---------------------------------------------------------------------------
__global__ __launch_bounds__(256) void k2a_colstats(const float* __restrict__ cmask)
{
    int b = blockIdx.y;
    int chunk = blockIdx.x;
    int q = threadIdx.x;
    const float* Sp = g_S + (size_t)(b*CC)*QQ;
    const float* cm = cmask + b*CC;
    float m = -INFINITY, s = 0.f;
    int cbeg = chunk * (CC/NCHUNK);
    for (int c = cbeg; c < cbeg + CC/NCHUNK; c++) {
        float v = Sp[(size_t)c*QQ + q] + NEGV * (1.f - cm[c]);
        if (v > m) { s = s * __expf(m - v); m = v; }
        s += __expf(v - m);
    }
    g_pm[(b*NCHUNK + chunk)*QQ + q] = m;
    g_ps[(b*NCHUNK + chunk)*QQ + q] = s;
}

// K2b: per-(b,c) row max/sumexp over q (Q=256, one warp per row)
__global__ __launch_bounds__(256) void k2b_rowstats(const float* __restrict__ qmask)
{
    int row  = (blockIdx.x * blockDim.x + threadIdx.x) >> 5;
    int lane = threadIdx.x & 31;
    if (row >= BB*CC) return;
    int b = row / CC;
    const float* Sp = g_S + (size_t)row * QQ;
    const float* qm = qmask + b*QQ;
    float v[8];
    float m = -INFINITY;
#pragma unroll
    for (int j = 0; j < 8; j++) {
        v[j] = Sp[j*32 + lane] + NEGV * (1.f - qm[j*32 + lane]);
        m = fmaxf(m, v[j]);
    }
#pragma unroll
    for (int o = 16; o > 0; o >>= 1) m = fmaxf(m, __shfl_xor_sync(0xffffffffu, m, o));
    float s = 0.f;
#pragma unroll
    for (int j = 0; j < 8; j++) s += __expf(v[j] - m);
#pragma unroll
    for (int o = 16; o > 0; o >>= 1) s += __shfl_xor_sync(0xffffffffu, s, o);
    if (lane == 0) { g_rowM[row] = m; g_rowZ[row] = s; }
}

// K2c: combine the NCHUNK partial column stats
__global__ void k2c_combine()
{
    int idx = blockIdx.x * blockDim.x + threadIdx.x;
    if (idx >= BB*QQ) return;
    int b = idx / QQ, q = idx - b*QQ;
    float m = -INFINITY;
#pragma unroll
    for (int ch = 0; ch < NCHUNK; ch++)
        m = fmaxf(m, g_pm[(b*NCHUNK + ch)*QQ + q]);
    float s = 0.f;
#pragma unroll
    for (int ch = 0; ch < NCHUNK; ch++)
        s += g_ps[(b*NCHUNK + ch)*QQ + q] * __expf(g_pm[(b*NCHUNK + ch)*QQ + q] - m);
    g_colM[idx] = m;
    g_colZ[idx] = s;
}

// ---------------------------------------------------------------------------
// K3: A[b,q,d] = sum_c softmax_c(S)[c,q] * xc[b,c,d]
// tiles: 64 q x 64 d, K = C = 1024 in 16-chunks
// ---------------------------------------------------------------------------
__global__ __launch_bounds__(256) void k3_A(const float* __restrict__ xc,
                                            const float* __restrict__ cmask)
{
    __shared__ float Ps[64][17];   // [q][kc]
    __shared__ float Xs[16][64];   // [kc][d]
    __shared__ float cM[64], ciZ[64];
    int b  = blockIdx.z;
    int q0 = blockIdx.y * 64;
    int d0 = blockIdx.x * 64;
    int tx = threadIdx.x, ty = threadIdx.y;
    int tid = ty*16 + tx;
    if (tid < 64) {
        cM[tid]  = g_colM[b*QQ + q0 + tid];
        ciZ[tid] = 1.f / g_colZ[b*QQ + q0 + tid];
    }
    __syncthreads();
    int pr = tid >> 4;          // 0..15 (c row within chunk)
    int po = (tid & 15) * 4;    // q / d offset within 64
    float acc[4][4] = {};
    const float* cm = cmask + b*CC;

    for (int ck = 0; ck < CC; ck += 16) {
        int c = ck + pr;
        float msk = NEGV * (1.f - cm[c]);
        float4 s4 = *(const float4*)&g_S[((size_t)(b*CC + c))*QQ + q0 + po];
        Ps[po+0][pr] = __expf(s4.x + msk - cM[po+0]) * ciZ[po+0];
        Ps[po+1][pr] = __expf(s4.y + msk - cM[po+1]) * ciZ[po+1];
        Ps[po+2][pr] = __expf(s4.z + msk - cM[po+2]) * ciZ[po+2];
        Ps[po+3][pr] = __expf(s4.w + msk - cM[po+3]) * ciZ[po+3];
        float4 x4 = *(const float4*)&xc[((size_t)(b*CC + c))*DD + d0 + po];
        Xs[pr][po+0] = x4.x; Xs[pr][po+1] = x4.y;
        Xs[pr][po+2] = x4.z; Xs[pr][po+3] = x4.w;
        __syncthreads();
#pragma unroll
        for (int k = 0; k < 16; k++) {
            float a[4];
#pragma unroll
            for (int i = 0; i < 4; i++) a[i] = Ps[ty*4+i][k];
            float4 xv = *(float4*)&Xs[k][tx*4];
#pragma unroll
            for (int i = 0; i < 4; i++) {
                acc[i][0] += a[i]*xv.x; acc[i][1] += a[i]*xv.y;
                acc[i][2] += a[i]*xv.z; acc[i][3] += a[i]*xv.w;
            }
        }
        __syncthreads();
    }
#pragma unroll
    for (int i = 0; i < 4; i++) {
        int q = q0 + ty*4 + i;
        float4 o = {acc[i][0], acc[i][1], acc[i][2], acc[i][3]};
        *(float4*)&g_A[((size_t)(b*QQ + q))*DD + d0 + tx*4] = o;
    }
}

// ---------------------------------------------------------------------------
// K4: c2q = softmax_q(S) @ xq ; q2c = softmax_q(S) @ A ; write 4-way concat
// tiles: 64 c x 64 d, K = Q = 256 in 16-chunks, dual accumulators
// ---------------------------------------------------------------------------
__global__ __launch_bounds__(256) void k4_out(const float* __restrict__ xc,
                                              const float* __restrict__ xq,
                                              const float* __restrict__ qmask,
                                              float* __restrict__ out)
{
    __shared__ float Ps[64][17];    // [c][kq]
    __shared__ float Xqs[16][64];
    __shared__ float Aqs[16][64];
    __shared__ float rM[64], riZ[64];
    __shared__ float qms[QQ];
    int b  = blockIdx.z;
    int c0 = blockIdx.y * 64;
    int d0 = blockIdx.x * 64;
    int tx = threadIdx.x, ty = threadIdx.y;
    int tid = ty*16 + tx;
    if (tid < 64) {
        rM[tid]  = g_rowM[b*CC + c0 + tid];
        riZ[tid] = 1.f / g_rowZ[b*CC + c0 + tid];
    }
    qms[tid] = NEGV * (1.f - qmask[b*QQ + tid]);
    __syncthreads();

    int pr = tid >> 2;        // 0..63 c row for Ps load
    int pq = (tid & 3) * 4;   // q offset 0..12
    int xr = tid >> 4;        // 0..15
    int xd = (tid & 15) * 4;
    float acc1[4][4] = {};
    float acc2[4][4] = {};

    for (int k0 = 0; k0 < QQ; k0 += 16) {
        float4 s4 = *(const float4*)&g_S[((size_t)(b*CC + c0 + pr))*QQ + k0 + pq];
        float m = rM[pr], iz = riZ[pr];
        Ps[pr][pq+0] = __expf(s4.x + qms[k0+pq+0] - m) * iz;
        Ps[pr][pq+1] = __expf(s4.y + qms[k0+pq+1] - m) * iz;
        Ps[pr][pq+2] = __expf(s4.z + qms[k0+pq+2] - m) * iz;
        Ps[pr][pq+3] = __expf(s4.w + qms[k0+pq+3] - m) * iz;
        float4 xv = *(const float4*)&xq[((size_t)(b*QQ + k0 + xr))*DD + d0 + xd];
        Xqs[xr][xd+0] = xv.x; Xqs[xr][xd+1] = xv.y;
        Xqs[xr][xd+2] = xv.z; Xqs[xr][xd+3] = xv.w;
        float4 av = *(const float4*)&g_A[((size_t)(b*QQ + k0 + xr))*DD + d0 + xd];
        Aqs[xr][xd+0] = av.x; Aqs[xr][xd+1] = av.y;
        Aqs[xr][xd+2] = av.z; Aqs[xr][xd+3] = av.w;
        __syncthreads();
#pragma unroll
        for (int k = 0; k < 16; k++) {
            float a[4];
#pragma unroll
            for (int i = 0; i < 4; i++) a[i] = Ps[ty*4+i][k];
            float4 x4 = *(float4*)&Xqs[k][tx*4];
            float4 a4 = *(float4*)&Aqs[k][tx*4];
#pragma unroll
            for (int i = 0; i < 4; i++) {
                acc1[i][0] += a[i]*x4.x; acc1[i][1] += a[i]*x4.y;
                acc1[i][2] += a[i]*x4.z; acc1[i][3] += a[i]*x4.w;
                acc2[i][0] += a[i]*a4.x; acc2[i][1] += a[i]*a4.y;
                acc2[i][2] += a[i]*a4.z; acc2[i][3] += a[i]*a4.w;
            }
        }
        __syncthreads();
    }

    int d = d0 + tx*4;
#pragma unroll
    for (int i = 0; i < 4; i++) {
        int c = c0 + ty*4 + i;
        size_t rbase = (size_t)(b*CC + c);
        float4 xcv = *(const float4*)&xc[rbase*DD + d];
        float* ob = out + rbase*OUTD;
        float4 c2q = {acc1[i][0], acc1[i][1], acc1[i][2], acc1[i][3]};
        float4 q2c = {acc2[i][0], acc2[i][1], acc2[i][2], acc2[i][3]};
        *(float4*)&ob[d] = xcv;
        *(float4*)&ob[DD + d] = c2q;
        float4 m1 = {xcv.x*c2q.x, xcv.y*c2q.y, xcv.z*c2q.z, xcv.w*c2q.w};
        *(float4*)&ob[2*DD + d] = m1;
        float4 m2 = {xcv.x*q2c.x, xcv.y*q2c.y, xcv.z*q2c.z, xcv.w*q2c.w};
        *(float4*)&ob[3*DD + d] = m2;
    }
}

// ---------------------------------------------------------------------------
extern "C" void kernel_launch(void* const* d_in, const int* in_sizes, int n_in,
                              void* d_out, int out_size)
{
    const float* xc   = (const float*)d_in[0];
    const float* xq   = (const float*)d_in[1];
    const float* cm   = (const float*)d_in[2];
    const float* qm   = (const float*)d_in[3];
    const float* W0   = (const float*)d_in[4];
    const float* W1   = (const float*)d_in[5];
    const float* W2   = (const float*)d_in[6];
    const float* bias = (const float*)d_in[7];
    float* out = (float*)d_out;

    dim3 blk(16, 16);
    k_s0<<<BB*CC/8, 256>>>(xc, W0);
    k_s1<<<BB*QQ/8, 256>>>(xq, W1);
    k1_S<<<dim3(QQ/64, CC/64, BB), blk>>>(xc, xq, W2, bias);
    k2a_colstats<<<dim3(NCHUNK, BB), 256>>>(cm);
    k2b_rowstats<<<BB*CC/8, 256>>>(qm);
    k2c_combine<<<BB*QQ/256, 256>>>();
    k3_A<<<dim3(DD/64, QQ/64, BB), blk>>>(xc, cm);
    k4_out<<<dim3(DD/64, CC/64, BB), blk>>>(xc, xq, qm, out);
}

// round 4
// speedup vs baseline: 1.5030x; 1.5030x over previous
#include <cuda_runtime.h>
#include <cuda_bf16.h>
#include <math.h>

#define BB 64
#define CC 1024
#define QQ 256
#define DD 128
#define OUTD (4*DD)
#define NEGV (-1e30f)
#define NCHUNK 8

// smem leading dims (bf16 elements); multiples of 8 (16B) for ldmatrix alignment
#define AS_LD 40    // 32 + 8 pad
#define BS_LD 136   // 128 + 8 pad

// ---- scratch (device globals: allocation-free) ----
__device__ float g_S[(size_t)BB*CC*QQ];      // raw S (incl. s0+s1+bias), 64 MB
__device__ float g_s0[BB*CC];                // x_cont@W0 + bias
__device__ float g_s1[BB*QQ];                // x_ques@W1
__device__ float g_pm[BB*NCHUNK*QQ];
__device__ float g_ps[BB*NCHUNK*QQ];
__device__ float g_colM[BB*QQ];
__device__ float g_colZ[BB*QQ];
__device__ float g_rowM[BB*CC];
__device__ float g_rowZ[BB*CC];
__device__ float g_A[(size_t)BB*QQ*DD];      // S_T @ x_cont, 8 MB

// ---------------------------------------------------------------------------
// MMA helpers: m16n8k16 bf16 -> f32, and ldmatrix loaders
// ---------------------------------------------------------------------------
__device__ __forceinline__ void mma16816(float* c, const unsigned* a, const unsigned* b)
{
    asm volatile(
        "mma.sync.aligned.m16n8k16.row.col.f32.bf16.bf16.f32 "
        "{%0,%1,%2,%3},{%4,%5,%6,%7},{%8,%9},{%0,%1,%2,%3};"
        : "+f"(c[0]), "+f"(c[1]), "+f"(c[2]), "+f"(c[3])
        : "r"(a[0]), "r"(a[1]), "r"(a[2]), "r"(a[3]), "r"(b[0]), "r"(b[1]));
}

__device__ __forceinline__ void ldsm4(unsigned* r, const __nv_bfloat16* p)
{
    unsigned addr = (unsigned)__cvta_generic_to_shared(p);
    asm volatile("ldmatrix.sync.aligned.m8n8.x4.shared.b16 {%0,%1,%2,%3},[%4];"
                 : "=r"(r[0]), "=r"(r[1]), "=r"(r[2]), "=r"(r[3]) : "r"(addr));
}

__device__ __forceinline__ void ldsm4t(unsigned* r, const __nv_bfloat16* p)
{
    unsigned addr = (unsigned)__cvta_generic_to_shared(p);
    asm volatile("ldmatrix.sync.aligned.m8n8.x4.trans.shared.b16 {%0,%1,%2,%3},[%4];"
                 : "=r"(r[0]), "=r"(r[1]), "=r"(r[2]), "=r"(r[3]) : "r"(addr));
}

__device__ __forceinline__ void split2(float x, __nv_bfloat16& h, __nv_bfloat16& l)
{
    h = __float2bfloat16(x);
    l = __float2bfloat16(x - __bfloat162float(h));
}

// load B-fragments (hi & lo) for a 64-wide n range at kstep ks
// Bs layout: [K rows][BS_LD] (n contiguous)
__device__ __forceinline__ void load_bfrags(unsigned bh[8][2], unsigned bl[8][2],
                                            const __nv_bfloat16* Bh, const __nv_bfloat16* Bl,
                                            int ks, int wn, int lane)
{
    int brow = ks + (lane & 7) + ((lane & 16) ? 8 : 0);
#pragma unroll
    for (int g4 = 0; g4 < 4; g4++) {
        int bcol = wn + g4*16 + ((lane & 8) ? 8 : 0);
        unsigned t[4];
        ldsm4t(t, &Bh[brow*BS_LD + bcol]);
        bh[2*g4][0] = t[0]; bh[2*g4][1] = t[2];
        bh[2*g4+1][0] = t[1]; bh[2*g4+1][1] = t[3];
        ldsm4t(t, &Bl[brow*BS_LD + bcol]);
        bl[2*g4][0] = t[0]; bl[2*g4][1] = t[2];
        bl[2*g4+1][0] = t[1]; bl[2*g4+1][1] = t[3];
    }
}

// ---------------------------------------------------------------------------
// projections: s0 = x_cont @ W0 + bias, s1 = x_ques @ W1  (one warp per row)
// ---------------------------------------------------------------------------
__device__ __forceinline__ float row_dot(const float* __restrict__ xr,
                                         const float* __restrict__ W, int lane)
{
    float s = 0.f;
#pragma unroll
    for (int d = 0; d < DD; d += 32) s += xr[d + lane] * W[d + lane];
#pragma unroll
    for (int o = 16; o > 0; o >>= 1) s += __shfl_xor_sync(0xffffffffu, s, o);
    return s;
}

__global__ void k_s0(const float* __restrict__ x, const float* __restrict__ W,
                     const float* __restrict__ bias)
{
    int warp = (blockIdx.x * blockDim.x + threadIdx.x) >> 5;
    int lane = threadIdx.x & 31;
    if (warp >= BB*CC) return;
    float s = row_dot(x + (size_t)warp * DD, W, lane);
    if (lane == 0) g_s0[warp] = s + bias[0];
}

__global__ void k_s1(const float* __restrict__ x, const float* __restrict__ W)
{
    int warp = (blockIdx.x * blockDim.x + threadIdx.x) >> 5;
    int lane = threadIdx.x & 31;
    if (warp >= BB*QQ) return;
    float s = row_dot(x + (size_t)warp * DD, W, lane);
    if (lane == 0) g_s1[warp] = s;
}

// ---------------------------------------------------------------------------
// K1: S[b,c,q] = sum_d (xc*W2)[c,d] * xq[q,d] + s0 + s1   (tensor cores)
// BLK 128c x 128q, K=128 in chunks of 32. 8 warps, warp tile 32x64.
// ---------------------------------------------------------------------------
__global__ __launch_bounds__(256) void k1_S(const float* __restrict__ xc,
                                            const float* __restrict__ xq,
                                            const float* __restrict__ W2)
{
    __shared__ __align__(16) __nv_bfloat16 Ah[128*AS_LD], Al[128*AS_LD];
    __shared__ __align__(16) __nv_bfloat16 Bh[32*BS_LD],  Bl[32*BS_LD];
    __shared__ float W2s[DD];

    int b  = blockIdx.z;
    int c0 = blockIdx.y * 128;
    int q0 = blockIdx.x * 128;
    int tid = threadIdx.x;
    int warp = tid >> 5, lane = tid & 31;
    int wm = (warp >> 1) * 32, wn = (warp & 1) * 64;
    if (tid < DD) W2s[tid] = W2[tid];

    float acc[2][8][4] = {};
    __syncthreads();

    for (int k0 = 0; k0 < DD; k0 += 32) {
        // A tile: 128c x 32d, scaled by W2, split hi/lo
#pragma unroll
        for (int i = 0; i < 4; i++) {
            int f = tid + i*256;
            int r = f >> 3, c4 = (f & 7) * 4;
            float4 v = *(const float4*)&xc[((size_t)(b*CC + c0 + r))*DD + k0 + c4];
            float w0 = v.x * W2s[k0+c4+0], w1 = v.y * W2s[k0+c4+1];
            float w2v = v.z * W2s[k0+c4+2], w3 = v.w * W2s[k0+c4+3];
            __nv_bfloat16 h, l;
            split2(w0, h, l); Ah[r*AS_LD + c4+0] = h; Al[r*AS_LD + c4+0] = l;
            split2(w1, h, l); Ah[r*AS_LD + c4+1] = h; Al[r*AS_LD + c4+1] = l;
            split2(w2v,h, l); Ah[r*AS_LD + c4+2] = h; Al[r*AS_LD + c4+2] = l;
            split2(w3, h, l); Ah[r*AS_LD + c4+3] = h; Al[r*AS_LD + c4+3] = l;
        }
        // B tile: [k=d 32][n=q 128] = xq^T, split hi/lo
#pragma unroll
        for (int i = 0; i < 4; i++) {
            int f = tid + i*256;
            int q = f >> 3, d4 = (f & 7) * 4;
            float4 v = *(const float4*)&xq[((size_t)(b*QQ + q0 + q))*DD + k0 + d4];
            __nv_bfloat16 h, l;
            split2(v.x, h, l); Bh[(d4+0)*BS_LD + q] = h; Bl[(d4+0)*BS_LD + q] = l;
            split2(v.y, h, l); Bh[(d4+1)*BS_LD + q] = h; Bl[(d4+1)*BS_LD + q] = l;
            split2(v.z, h, l); Bh[(d4+2)*BS_LD + q] = h; Bl[(d4+2)*BS_LD + q] = l;
            split2(v.w, h, l); Bh[(d4+3)*BS_LD + q] = h; Bl[(d4+3)*BS_LD + q] = l;
        }
        __syncthreads();
#pragma unroll
        for (int ks = 0; ks < 32; ks += 16) {
            unsigned ah[2][4], al[2][4];
            int arow = wm + (lane & 15);
            int acol = ks + ((lane & 16) ? 8 : 0);
            ldsm4(ah[0], &Ah[arow*AS_LD + acol]);
            ldsm4(ah[1], &Ah[(arow+16)*AS_LD + acol]);
            ldsm4(al[0], &Al[arow*AS_LD + acol]);
            ldsm4(al[1], &Al[(arow+16)*AS_LD + acol]);
            unsigned bh[8][2], bl[8][2];
            load_bfrags(bh, bl, Bh, Bl, ks, wn, lane);
#pragma unroll
            for (int mi = 0; mi < 2; mi++)
#pragma unroll
                for (int nj = 0; nj < 8; nj++) {
                    mma16816(acc[mi][nj], ah[mi], bh[nj]);
                    mma16816(acc[mi][nj], ah[mi], bl[nj]);
                    mma16816(acc[mi][nj], al[mi], bh[nj]);
                }
        }
        __syncthreads();
    }

    // epilogue: + s0 + s1, write S
    int g = lane >> 2, tg = lane & 3;
#pragma unroll
    for (int mi = 0; mi < 2; mi++) {
#pragma unroll
        for (int nj = 0; nj < 8; nj++) {
            int c_ = c0 + wm + mi*16 + g;
            int q_ = q0 + wn + nj*8 + tg*2;
            float s0a = g_s0[b*CC + c_];
            float s0b = g_s0[b*CC + c_ + 8];
            float s1a = g_s1[b*QQ + q_], s1b = g_s1[b*QQ + q_ + 1];
            float2 o0 = {acc[mi][nj][0] + s0a + s1a, acc[mi][nj][1] + s0a + s1b};
            *(float2*)&g_S[((size_t)(b*CC + c_))*QQ + q_] = o0;
            float2 o1 = {acc[mi][nj][2] + s0b + s1a, acc[mi][nj][3] + s0b + s1b};
            *(float2*)&g_S[((size_t)(b*CC + c_ + 8))*QQ + q_] = o1;
        }
    }
}

// ---------------------------------------------------------------------------
// K2a: per-(b,q) partial max/sumexp over c (per 128-c chunk)
// ---------------------------------------------------------------------------
__global__ __launch_bounds__(256) void k2a_colstats(const float* __restrict__ cmask)
{
    int b = blockIdx.y;
    int chunk = blockIdx.x;
    int q = threadIdx.x;
    const float* Sp = g_S + (size_t)(b*CC)*QQ;
    const float* cm = cmask + b*CC;
    float m = -INFINITY, s = 0.f;
    int cbeg = chunk * (CC/NCHUNK);
    for (int c = cbeg; c < cbeg + CC/NCHUNK; c++) {
        float v = Sp[(size_t)c*QQ + q] + NEGV * (1.f - cm[c]);
        if (v > m) { s = s * __expf(m - v); m = v; }
        s += __expf(v - m);
    }
    g_pm[(b*NCHUNK + chunk)*QQ + q] = m;
    g_ps[(b*NCHUNK + chunk)*QQ + q] = s;
}

// K2b: per-(b,c) row max/sumexp over q
__global__ __launch_bounds__(256) void k2b_rowstats(const float* __restrict__ qmask)
{
    int row  = (blockIdx.x * blockDim.x + threadIdx.x) >> 5;
    int lane = threadIdx.x & 31;
    if (row >= BB*CC) return;
    int b = row / CC;
    const float* Sp = g_S + (size_t)row * QQ;
    const float* qm = qmask + b*QQ;
    float v[8];
    float m = -INFINITY;
#pragma unroll
    for (int j = 0; j < 8; j++) {
        v[j] = Sp[j*32 + lane] + NEGV * (1.f - qm[j*32 + lane]);
        m = fmaxf(m, v[j]);
    }
#pragma unroll
    for (int o = 16; o > 0; o >>= 1) m = fmaxf(m, __shfl_xor_sync(0xffffffffu, m, o));
    float s = 0.f;
#pragma unroll
    for (int j = 0; j < 8; j++) s += __expf(v[j] - m);
#pragma unroll
    for (int o = 16; o > 0; o >>= 1) s += __shfl_xor_sync(0xffffffffu, s, o);
    if (lane == 0) { g_rowM[row] = m; g_rowZ[row] = s; }
}

__global__ void k2c_combine()
{
    int idx = blockIdx.x * blockDim.x + threadIdx.x;
    if (idx >= BB*QQ) return;
    int b = idx / QQ, q = idx - b*QQ;
    float m = -INFINITY;
#pragma unroll
    for (int ch = 0; ch < NCHUNK; ch++)
        m = fmaxf(m, g_pm[(b*NCHUNK + ch)*QQ + q]);
    float s = 0.f;
#pragma unroll
    for (int ch = 0; ch < NCHUNK; ch++)
        s += g_ps[(b*NCHUNK + ch)*QQ + q] * __expf(g_pm[(b*NCHUNK + ch)*QQ + q] - m);
    g_colM[idx] = m;
    g_colZ[idx] = s;
}

// ---------------------------------------------------------------------------
// K3: A[b,q,d] = sum_c Pcol[c,q] * xc[c,d]  (tensor cores)
// BLK 64q x 128d, K=C in chunks of 32. warp tile 16x64.
// ---------------------------------------------------------------------------
__global__ __launch_bounds__(256) void k3_A(const float* __restrict__ xc,
                                            const float* __restrict__ cmask)
{
    __shared__ __align__(16) __nv_bfloat16 Ah[64*AS_LD], Al[64*AS_LD];
    __shared__ __align__(16) __nv_bfloat16 Bh[32*BS_LD],  Bl[32*BS_LD];
    __shared__ float cM[64], ciZ[64], cmn[32];

    int b  = blockIdx.z;
    int q0 = blockIdx.x * 64;
    int tid = threadIdx.x;
    int warp = tid >> 5, lane = tid & 31;
    int wm = (warp >> 1) * 16, wn = (warp & 1) * 64;
    if (tid < 64) {
        cM[tid]  = g_colM[b*QQ + q0 + tid];
        ciZ[tid] = 1.f / g_colZ[b*QQ + q0 + tid];
    }
    float acc[8][4] = {};

    for (int cc0 = 0; cc0 < CC; cc0 += 32) {
        if (tid < 32) cmn[tid] = NEGV * (1.f - cmask[b*CC + cc0 + tid]);
        __syncthreads();
        // A tile: P^T [q 64][c 32]
#pragma unroll
        for (int i = 0; i < 2; i++) {
            int f = tid + i*256;
            int c = f >> 4, q4 = (f & 15) * 4;
            float4 s4 = *(const float4*)&g_S[((size_t)(b*CC + cc0 + c))*QQ + q0 + q4];
            float msk = cmn[c];
            float p0 = __expf(s4.x + msk - cM[q4+0]) * ciZ[q4+0];
            float p1 = __expf(s4.y + msk - cM[q4+1]) * ciZ[q4+1];
            float p2 = __expf(s4.z + msk - cM[q4+2]) * ciZ[q4+2];
            float p3 = __expf(s4.w + msk - cM[q4+3]) * ciZ[q4+3];
            __nv_bfloat16 h, l;
            split2(p0, h, l); Ah[(q4+0)*AS_LD + c] = h; Al[(q4+0)*AS_LD + c] = l;
            split2(p1, h, l); Ah[(q4+1)*AS_LD + c] = h; Al[(q4+1)*AS_LD + c] = l;
            split2(p2, h, l); Ah[(q4+2)*AS_LD + c] = h; Al[(q4+2)*AS_LD + c] = l;
            split2(p3, h, l); Ah[(q4+3)*AS_LD + c] = h; Al[(q4+3)*AS_LD + c] = l;
        }
        // B tile: [k=c 32][n=d 128] = xc (direct)
#pragma unroll
        for (int i = 0; i < 4; i++) {
            int f = tid + i*256;
            int c = f >> 5, d4 = (f & 31) * 4;
            float4 v = *(const float4*)&xc[((size_t)(b*CC + cc0 + c))*DD + d4];
            __nv_bfloat16 h, l;
            split2(v.x, h, l); Bh[c*BS_LD + d4+0] = h; Bl[c*BS_LD + d4+0] = l;
            split2(v.y, h, l); Bh[c*BS_LD + d4+1] = h; Bl[c*BS_LD + d4+1] = l;
            split2(v.z, h, l); Bh[c*BS_LD + d4+2] = h; Bl[c*BS_LD + d4+2] = l;
            split2(v.w, h, l); Bh[c*BS_LD + d4+3] = h; Bl[c*BS_LD + d4+3] = l;
        }
        __syncthreads();
#pragma unroll
        for (int ks = 0; ks < 32; ks += 16) {
            unsigned ah[4], al[4];
            int arow = wm + (lane & 15);
            int acol = ks + ((lane & 16) ? 8 : 0);
            ldsm4(ah, &Ah[arow*AS_LD + acol]);
            ldsm4(al, &Al[arow*AS_LD + acol]);
            unsigned bh[8][2], bl[8][2];
            load_bfrags(bh, bl, Bh, Bl, ks, wn, lane);
#pragma unroll
            for (int nj = 0; nj < 8; nj++) {
                mma16816(acc[nj], ah, bh[nj]);
                mma16816(acc[nj], ah, bl[nj]);
                mma16816(acc[nj], al, bh[nj]);
            }
        }
        __syncthreads();
    }

    int g = lane >> 2, tg = lane & 3;
#pragma unroll
    for (int nj = 0; nj < 8; nj++) {
        int q_ = q0 + wm + g;
        int d_ = wn + nj*8 + tg*2;
        float2 o0 = {acc[nj][0], acc[nj][1]};
        *(float2*)&g_A[((size_t)(b*QQ + q_))*DD + d_] = o0;
        float2 o1 = {acc[nj][2], acc[nj][3]};
        *(float2*)&g_A[((size_t)(b*QQ + q_ + 8))*DD + d_] = o1;
    }
}

// ---------------------------------------------------------------------------
// K4: c2q = Prow @ xq ; q2c = Prow @ A ; write concat  (tensor cores, dual)
// BLK 64c x 128d, K=Q in chunks of 32. warp tile 16x64.
// ---------------------------------------------------------------------------
__global__ __launch_bounds__(256) void k4_out(const float* __restrict__ xc,
                                              const float* __restrict__ xq,
                                              const float* __restrict__ qmask,
                                              float* __restrict__ out)
{
    __shared__ __align__(16) __nv_bfloat16 Ah[64*AS_LD],  Al[64*AS_LD];
    __shared__ __align__(16) __nv_bfloat16 B1h[32*BS_LD], B1l[32*BS_LD];
    __shared__ __align__(16) __nv_bfloat16 B2h[32*BS_LD], B2l[32*BS_LD];
    __shared__ float rM[64], riZ[64], qmn[QQ];

    int b  = blockIdx.z;
    int c0 = blockIdx.x * 64;
    int tid = threadIdx.x;
    int warp = tid >> 5, lane = tid & 31;
    int wm = (warp >> 1) * 16, wn = (warp & 1) * 64;
    if (tid < 64) {
        rM[tid]  = g_rowM[b*CC + c0 + tid];
        riZ[tid] = 1.f / g_rowZ[b*CC + c0 + tid];
    }
    qmn[tid] = NEGV * (1.f - qmask[b*QQ + tid]);
    __syncthreads();

    float acc1[8][4] = {};
    float acc2[8][4] = {};

    for (int qq0 = 0; qq0 < QQ; qq0 += 32) {
        // A tile: Prow [c 64][q 32] (direct layout)
#pragma unroll
        for (int i = 0; i < 2; i++) {
            int f = tid + i*256;
            int c = f >> 3, q4 = (f & 7) * 4;
            float4 s4 = *(const float4*)&g_S[((size_t)(b*CC + c0 + c))*QQ + qq0 + q4];
            float m = rM[c], iz = riZ[c];
            float p0 = __expf(s4.x + qmn[qq0+q4+0] - m) * iz;
            float p1 = __expf(s4.y + qmn[qq0+q4+1] - m) * iz;
            float p2 = __expf(s4.z + qmn[qq0+q4+2] - m) * iz;
            float p3 = __expf(s4.w + qmn[qq0+q4+3] - m) * iz;
            __nv_bfloat16 h, l;
            split2(p0, h, l); Ah[c*AS_LD + q4+0] = h; Al[c*AS_LD + q4+0] = l;
            split2(p1, h, l); Ah[c*AS_LD + q4+1] = h; Al[c*AS_LD + q4+1] = l;
            split2(p2, h, l); Ah[c*AS_LD + q4+2] = h; Al[c*AS_LD + q4+2] = l;
            split2(p3, h, l); Ah[c*AS_LD + q4+3] = h; Al[c*AS_LD + q4+3] = l;
        }
        // B tiles: [k=q 32][n=d 128] xq and g_A (direct)
#pragma unroll
        for (int i = 0; i < 4; i++) {
            int f = tid + i*256;
            int q = f >> 5, d4 = (f & 31) * 4;
            float4 v = *(const float4*)&xq[((size_t)(b*QQ + qq0 + q))*DD + d4];
            __nv_bfloat16 h, l;
            split2(v.x, h, l); B1h[q*BS_LD + d4+0] = h; B1l[q*BS_LD + d4+0] = l;
            split2(v.y, h, l); B1h[q*BS_LD + d4+1] = h; B1l[q*BS_LD + d4+1] = l;
            split2(v.z, h, l); B1h[q*BS_LD + d4+2] = h; B1l[q*BS_LD + d4+2] = l;
            split2(v.w, h, l); B1h[q*BS_LD + d4+3] = h; B1l[q*BS_LD + d4+3] = l;
            float4 a4 = *(const float4*)&g_A[((size_t)(b*QQ + qq0 + q))*DD + d4];
            split2(a4.x, h, l); B2h[q*BS_LD + d4+0] = h; B2l[q*BS_LD + d4+0] = l;
            split2(a4.y, h, l); B2h[q*BS_LD + d4+1] = h; B2l[q*BS_LD + d4+1] = l;
            split2(a4.z, h, l); B2h[q*BS_LD + d4+2] = h; B2l[q*BS_LD + d4+2] = l;
            split2(a4.w, h, l); B2h[q*BS_LD + d4+3] = h; B2l[q*BS_LD + d4+3] = l;
        }
        __syncthreads();
#pragma unroll
        for (int ks = 0; ks < 32; ks += 16) {
            unsigned ah[4], al[4];
            int arow = wm + (lane & 15);
            int acol = ks + ((lane & 16) ? 8 : 0);
            ldsm4(ah, &Ah[arow*AS_LD + acol]);
            ldsm4(al, &Al[arow*AS_LD + acol]);
            unsigned bh[8][2], bl[8][2];
            load_bfrags(bh, bl, B1h, B1l, ks, wn, lane);
#pragma unroll
            for (int nj = 0; nj < 8; nj++) {
                mma16816(acc1[nj], ah, bh[nj]);
                mma16816(acc1[nj], ah, bl[nj]);
                mma16816(acc1[nj], al, bh[nj]);
            }
            load_bfrags(bh, bl, B2h, B2l, ks, wn, lane);
#pragma unroll
            for (int nj = 0; nj < 8; nj++) {
                mma16816(acc2[nj], ah, bh[nj]);
                mma16816(acc2[nj], ah, bl[nj]);
                mma16816(acc2[nj], al, bh[nj]);
            }
        }
        __syncthreads();
    }

    int g = lane >> 2, tg = lane & 3;
#pragma unroll
    for (int nj = 0; nj < 8; nj++) {
        int d_ = wn + nj*8 + tg*2;
#pragma unroll
        for (int half = 0; half < 2; half++) {
            int c_ = c0 + wm + g + half*8;
            size_t rbase = (size_t)(b*CC + c_);
            float2 xv = *(const float2*)&xc[rbase*DD + d_];
            float2 c2q = {half ? acc1[nj][2] : acc1[nj][0],
                          half ? acc1[nj][3] : acc1[nj][1]};
            float2 q2c = {half ? acc2[nj][2] : acc2[nj][0],
                          half ? acc2[nj][3] : acc2[nj][1]};
            float* ob = out + rbase*OUTD;
            *(float2*)&ob[d_] = xv;
            *(float2*)&ob[DD + d_] = c2q;
            float2 m1 = {xv.x*c2q.x, xv.y*c2q.y};
            *(float2*)&ob[2*DD + d_] = m1;
            float2 m2 = {xv.x*q2c.x, xv.y*q2c.y};
            *(float2*)&ob[3*DD + d_] = m2;
        }
    }
}

// ---------------------------------------------------------------------------
extern "C" void kernel_launch(void* const* d_in, const int* in_sizes, int n_in,
                              void* d_out, int out_size)
{
    const float* xc   = (const float*)d_in[0];
    const float* xq   = (const float*)d_in[1];
    const float* cm   = (const float*)d_in[2];
    const float* qm   = (const float*)d_in[3];
    const float* W0   = (const float*)d_in[4];
    const float* W1   = (const float*)d_in[5];
    const float* W2   = (const float*)d_in[6];
    const float* bias = (const float*)d_in[7];
    float* out = (float*)d_out;

    k_s0<<<BB*CC/8, 256>>>(xc, W0, bias);
    k_s1<<<BB*QQ/8, 256>>>(xq, W1);
    k1_S<<<dim3(QQ/128, CC/128, BB), 256>>>(xc, xq, W2);
    k2a_colstats<<<dim3(NCHUNK, BB), 256>>>(cm);
    k2b_rowstats<<<BB*CC/8, 256>>>(qm);
    k2c_combine<<<BB*QQ/256, 256>>>();
    k3_A<<<dim3(QQ/64, 1, BB), 256>>>(xc, cm);
    k4_out<<<dim3(CC/64, 1, BB), 256>>>(xc, xq, qm, out);
}